// round 2
// baseline (speedup 1.0000x reference)
#include <cuda_runtime.h>
#include <cuda_bf16.h>

#define N_NODES 100000
#define N_EDGES 3200000
#define HID 128
#define N_GRAPHS 512

// ---------------- scratch (device globals; no allocation allowed) ----------
__device__ float g_T[(size_t)N_NODES * HID];     // tmp = act(input) @ W
__device__ float g_A[(size_t)N_NODES * HID];     // aggregated output
__device__ float g_norm[N_EDGES];
__device__ float g_deg[N_NODES];
__device__ float g_dinv[N_NODES];
__device__ float g_pool[N_GRAPHS * HID];
__device__ float g_cnt[N_GRAPHS];

// ---------------- degree / norm ----------------
__global__ void k_init_deg() {
    int i = blockIdx.x * blockDim.x + threadIdx.x;
    if (i < N_NODES) g_deg[i] = 1.0f;   // self-loop weight
}

__global__ void k_accum_deg(const int* __restrict__ ei, const float* __restrict__ ew) {
    int e = blockIdx.x * blockDim.x + threadIdx.x;
    if (e >= N_EDGES) return;
    int dst = ei[N_EDGES + e];
    atomicAdd(&g_deg[dst], ew[e]);
}

__global__ void k_dinv() {
    int i = blockIdx.x * blockDim.x + threadIdx.x;
    if (i < N_NODES) g_dinv[i] = rsqrtf(g_deg[i]);   // deg >= 1 always
}

__global__ void k_norm(const int* __restrict__ ei, const float* __restrict__ ew) {
    int e = blockIdx.x * blockDim.x + threadIdx.x;
    if (e >= N_EDGES) return;
    int src = ei[e], dst = ei[N_EDGES + e];
    g_norm[e] = g_dinv[src] * ew[e] * g_dinv[dst];
}

// ---------------- GEMM: T = act(X) @ W ----------------
// Block handles 32 rows x 128 cols. 256 threads.
// smem: W 64KB + X-tile 16KB = 80KB dynamic.
#define TILE_R 32
__global__ void k_gemm(const float* __restrict__ X, const float* __restrict__ W,
                       float* __restrict__ T, int relu_in) {
    extern __shared__ float sh[];
    float* Ws = sh;               // 128*128
    float* Xs = sh + HID * HID;   // TILE_R*128
    int tid = threadIdx.x;
    int row0 = blockIdx.x * TILE_R;

    const float4* W4 = (const float4*)W;
    float4* Ws4 = (float4*)Ws;
    #pragma unroll 4
    for (int i = tid; i < HID * HID / 4; i += 256) Ws4[i] = W4[i];

    const float4* X4 = (const float4*)(X + (size_t)row0 * HID);
    float4* Xs4 = (float4*)Xs;
    #pragma unroll
    for (int i = tid; i < TILE_R * HID / 4; i += 256) {
        float4 v = X4[i];
        if (relu_in) {
            v.x = fmaxf(v.x, 0.f); v.y = fmaxf(v.y, 0.f);
            v.z = fmaxf(v.z, 0.f); v.w = fmaxf(v.w, 0.f);
        }
        Xs4[i] = v;
    }
    __syncthreads();

    int cg = tid & 31;        // column group: cols cg*4 .. cg*4+3
    int rg = tid >> 5;        // row group:    rows rg*4 .. rg*4+3
    float acc[4][4];
    #pragma unroll
    for (int i = 0; i < 4; i++)
        #pragma unroll
        for (int j = 0; j < 4; j++) acc[i][j] = 0.f;

    #pragma unroll 4
    for (int k = 0; k < HID; k++) {
        float4 w = *(const float4*)&Ws[k * HID + cg * 4];
        #pragma unroll
        for (int i = 0; i < 4; i++) {
            float xv = Xs[(rg * 4 + i) * HID + k];
            acc[i][0] += xv * w.x;
            acc[i][1] += xv * w.y;
            acc[i][2] += xv * w.z;
            acc[i][3] += xv * w.w;
        }
    }
    #pragma unroll
    for (int i = 0; i < 4; i++) {
        int r = row0 + rg * 4 + i;
        *(float4*)&T[(size_t)r * HID + cg * 4] =
            make_float4(acc[i][0], acc[i][1], acc[i][2], acc[i][3]);
    }
}

// ---------------- A[i] = T[i]*dinv[i]^2 + b  (self-loop + bias) ----------------
__global__ void k_init_out(const float* __restrict__ b) {
    int idx = blockIdx.x * blockDim.x + threadIdx.x;   // over N_NODES*32 float4s
    if (idx >= N_NODES * (HID / 4)) return;
    int i = idx >> 5;
    int c4 = idx & 31;
    float di = g_dinv[i];
    float w = di * di;
    float4 t = ((const float4*)g_T)[idx];
    float4 bb = ((const float4*)b)[c4];
    float4 r = make_float4(t.x * w + bb.x, t.y * w + bb.y,
                           t.z * w + bb.z, t.w * w + bb.w);
    ((float4*)g_A)[idx] = r;
}

// ---------------- edge scatter: A[dst] += T[src] * norm ----------------
// one warp per edge; lane handles one float4 (128 floats = 32 lanes * 4)
__global__ void k_scatter(const int* __restrict__ ei) {
    int w = (blockIdx.x * blockDim.x + threadIdx.x) >> 5;
    int lane = threadIdx.x & 31;
    if (w >= N_EDGES) return;
    int src = __ldg(&ei[w]);
    int dst = __ldg(&ei[N_EDGES + w]);
    float nw = __ldg(&g_norm[w]);
    float4 v = ((const float4*)(g_T + (size_t)src * HID))[lane];
    v.x *= nw; v.y *= nw; v.z *= nw; v.w *= nw;
    float* d = g_A + (size_t)dst * HID + lane * 4;
    asm volatile("red.global.add.v4.f32 [%0], {%1,%2,%3,%4};"
                 :: "l"(d), "f"(v.x), "f"(v.y), "f"(v.z), "f"(v.w) : "memory");
}

// ---------------- pooling ----------------
__global__ void k_zero_pool() {
    int i = blockIdx.x * blockDim.x + threadIdx.x;
    if (i < N_GRAPHS * HID) g_pool[i] = 0.f;
    if (i < N_GRAPHS) g_cnt[i] = 0.f;
}

__global__ void k_pool(const int* __restrict__ batch) {
    int w = (blockIdx.x * blockDim.x + threadIdx.x) >> 5;
    int lane = threadIdx.x & 31;
    if (w >= N_NODES) return;
    int g = __ldg(&batch[w]);
    float4 v = ((const float4*)(g_A + (size_t)w * HID))[lane];
    v.x = fmaxf(v.x, 0.f); v.y = fmaxf(v.y, 0.f);
    v.z = fmaxf(v.z, 0.f); v.w = fmaxf(v.w, 0.f);
    float* d = g_pool + g * HID + lane * 4;
    asm volatile("red.global.add.v4.f32 [%0], {%1,%2,%3,%4};"
                 :: "l"(d), "f"(v.x), "f"(v.y), "f"(v.z), "f"(v.w) : "memory");
    if (lane == 0) atomicAdd(&g_cnt[g], 1.0f);
}

// ---------------- head: out[g] = sigmoid(mean_pool . Wc + bc) ----------------
__global__ void k_final(const float* __restrict__ Wc, const float* __restrict__ bc,
                        float* __restrict__ out) {
    int g = blockIdx.x;
    int c = threadIdx.x;     // 128
    float cn = fmaxf(g_cnt[g], 1.0f);
    float v = g_pool[g * HID + c] / cn * Wc[c];
    #pragma unroll
    for (int o = 16; o > 0; o >>= 1) v += __shfl_down_sync(0xffffffffu, v, o);
    __shared__ float ss[4];
    if ((c & 31) == 0) ss[c >> 5] = v;
    __syncthreads();
    if (c == 0) {
        float s = ss[0] + ss[1] + ss[2] + ss[3] + bc[0];
        out[g] = 1.0f / (1.0f + expf(-s));
    }
}

// ---------------- launch ----------------
extern "C" void kernel_launch(void* const* d_in, const int* in_sizes, int n_in,
                              void* d_out, int out_size) {
    const float* x   = (const float*)d_in[0];
    const int*   ei  = (const int*)d_in[1];
    const float* ew  = (const float*)d_in[2];
    const int*   bat = (const int*)d_in[3];
    const float* W[4]  = { (const float*)d_in[4], (const float*)d_in[6],
                           (const float*)d_in[8], (const float*)d_in[10] };
    const float* B[4]  = { (const float*)d_in[5], (const float*)d_in[7],
                           (const float*)d_in[9], (const float*)d_in[11] };
    const float* Wc  = (const float*)d_in[12];
    const float* bc  = (const float*)d_in[13];
    float* out = (float*)d_out;

    // stateless: set attribute + resolve symbols on every call (cheap queries,
    // not stream operations — capture-legal)
    const int smem = (HID * HID + TILE_R * HID) * sizeof(float);
    cudaFuncSetAttribute(k_gemm, cudaFuncAttributeMaxDynamicSharedMemorySize, smem);

    float* T_ptr; cudaGetSymbolAddress((void**)&T_ptr, g_T);
    float* A_ptr; cudaGetSymbolAddress((void**)&A_ptr, g_A);

    // degree + norm
    k_init_deg<<<(N_NODES + 255) / 256, 256>>>();
    k_accum_deg<<<(N_EDGES + 255) / 256, 256>>>(ei, ew);
    k_dinv<<<(N_NODES + 255) / 256, 256>>>();
    k_norm<<<(N_EDGES + 255) / 256, 256>>>(ei, ew);

    const int gemm_grid = N_NODES / TILE_R;                  // 3125 (exact)
    const int init_grid = (N_NODES * (HID / 4) + 255) / 256; // float4 elems
    const int scat_grid = (N_EDGES * 32 + 255) / 256;        // warp per edge

    // 4 GCN layers
    for (int l = 0; l < 4; l++) {
        const float* in = (l == 0) ? x : A_ptr;
        int relu_in = (l == 0) ? 0 : 1;
        k_gemm<<<gemm_grid, 256, smem>>>(in, W[l], T_ptr, relu_in);
        k_init_out<<<init_grid, 256>>>(B[l]);
        k_scatter<<<scat_grid, 256>>>(ei);
    }

    // pooling + head
    k_zero_pool<<<(N_GRAPHS * HID + 255) / 256, 256>>>();
    k_pool<<<(N_NODES * 32 + 255) / 256, 256>>>(bat);
    k_final<<<N_GRAPHS, HID>>>(Wc, bc, out);
}

// round 3
// speedup vs baseline: 2.0117x; 2.0117x over previous
#include <cuda_runtime.h>
#include <cuda_bf16.h>

#define N_NODES 100000
#define N_EDGES 3200000
#define HID 128
#define N_GRAPHS 512

// ---------------- scratch (device globals; no allocation allowed) ----------
__device__ float g_T[(size_t)N_NODES * HID];     // tmp = act(input) @ W
__device__ float g_A[(size_t)N_NODES * HID];     // aggregated output
__device__ float g_deg[N_NODES];
__device__ float g_dinv[N_NODES];
__device__ float g_pool[N_GRAPHS * HID];
__device__ float g_cnt[N_GRAPHS];
// CSR (by destination)
__device__ int   g_row_ptr[N_NODES + 1];
__device__ int   g_row_fill[N_NODES];
__device__ int   g_col_src[N_EDGES];
__device__ float g_col_w[N_EDGES];
__device__ int   g_hist[N_NODES];

// ---------------- degree / norm ----------------
__global__ void k_init_deg() {
    int i = blockIdx.x * blockDim.x + threadIdx.x;
    if (i < N_NODES) { g_deg[i] = 1.0f; g_hist[i] = 0; }   // self-loop weight
}

__global__ void k_accum_deg(const int* __restrict__ ei, const float* __restrict__ ew) {
    int e = blockIdx.x * blockDim.x + threadIdx.x;
    if (e >= N_EDGES) return;
    int dst = ei[N_EDGES + e];
    atomicAdd(&g_deg[dst], ew[e]);
    atomicAdd(&g_hist[dst], 1);
}

__global__ void k_dinv() {
    int i = blockIdx.x * blockDim.x + threadIdx.x;
    if (i < N_NODES) g_dinv[i] = rsqrtf(g_deg[i]);   // deg >= 1 always
}

// ---------------- single-block exclusive prefix scan over g_hist ----------
#define SCAN_T 1024
__global__ void k_scan() {
    __shared__ float dummy_guard;  (void)dummy_guard;
    __shared__ int partial[SCAN_T];
    int t = threadIdx.x;
    const int chunk = (N_NODES + SCAN_T - 1) / SCAN_T;   // 98
    int beg = t * chunk;
    int end = min(beg + chunk, N_NODES);
    int s = 0;
    for (int i = beg; i < end; i++) s += g_hist[i];
    partial[t] = s;
    __syncthreads();
    // Hillis-Steele inclusive scan over partials
    #pragma unroll
    for (int o = 1; o < SCAN_T; o <<= 1) {
        int v = (t >= o) ? partial[t - o] : 0;
        __syncthreads();
        partial[t] += v;
        __syncthreads();
    }
    int run = (t == 0) ? 0 : partial[t - 1];   // exclusive base for this chunk
    for (int i = beg; i < end; i++) {
        int h = g_hist[i];
        g_row_ptr[i] = run;
        g_row_fill[i] = run;
        run += h;
    }
    if (t == SCAN_T - 1) g_row_ptr[N_NODES] = run;   // == N_EDGES
}

// ---------------- fill CSR: col_src + fused norm weight --------------------
__global__ void k_fill(const int* __restrict__ ei, const float* __restrict__ ew) {
    int e = blockIdx.x * blockDim.x + threadIdx.x;
    if (e >= N_EDGES) return;
    int src = ei[e], dst = ei[N_EDGES + e];
    int pos = atomicAdd(&g_row_fill[dst], 1);
    g_col_src[pos] = src;
    g_col_w[pos] = g_dinv[src] * ew[e] * g_dinv[dst];
}

// ---------------- GEMM: T = act(X) @ W ----------------
#define TILE_R 32
__global__ void k_gemm(const float* __restrict__ X, const float* __restrict__ W,
                       float* __restrict__ T, int relu_in) {
    extern __shared__ float sh[];
    float* Ws = sh;               // 128*128
    float* Xs = sh + HID * HID;   // TILE_R*128
    int tid = threadIdx.x;
    int row0 = blockIdx.x * TILE_R;

    const float4* W4 = (const float4*)W;
    float4* Ws4 = (float4*)Ws;
    #pragma unroll 4
    for (int i = tid; i < HID * HID / 4; i += 256) Ws4[i] = W4[i];

    const float4* X4 = (const float4*)(X + (size_t)row0 * HID);
    float4* Xs4 = (float4*)Xs;
    #pragma unroll
    for (int i = tid; i < TILE_R * HID / 4; i += 256) {
        float4 v = X4[i];
        if (relu_in) {
            v.x = fmaxf(v.x, 0.f); v.y = fmaxf(v.y, 0.f);
            v.z = fmaxf(v.z, 0.f); v.w = fmaxf(v.w, 0.f);
        }
        Xs4[i] = v;
    }
    __syncthreads();

    int cg = tid & 31;        // cols cg*4 .. cg*4+3
    int rg = tid >> 5;        // rows rg*4 .. rg*4+3
    float acc[4][4];
    #pragma unroll
    for (int i = 0; i < 4; i++)
        #pragma unroll
        for (int j = 0; j < 4; j++) acc[i][j] = 0.f;

    #pragma unroll 4
    for (int k = 0; k < HID; k++) {
        float4 w = *(const float4*)&Ws[k * HID + cg * 4];
        #pragma unroll
        for (int i = 0; i < 4; i++) {
            float xv = Xs[(rg * 4 + i) * HID + k];
            acc[i][0] += xv * w.x;
            acc[i][1] += xv * w.y;
            acc[i][2] += xv * w.z;
            acc[i][3] += xv * w.w;
        }
    }
    #pragma unroll
    for (int i = 0; i < 4; i++) {
        int r = row0 + rg * 4 + i;
        *(float4*)&T[(size_t)r * HID + cg * 4] =
            make_float4(acc[i][0], acc[i][1], acc[i][2], acc[i][3]);
    }
}

// ---------------- aggregate: A[d] = b + T[d]*dinv[d]^2 + sum_e w_e*T[src_e] ----
// warp per destination node; lane owns one float4 (4 columns)
__global__ void k_aggregate(const float* __restrict__ b) {
    int node = (blockIdx.x * blockDim.x + threadIdx.x) >> 5;
    int lane = threadIdx.x & 31;
    if (node >= N_NODES) return;

    int beg = __ldg(&g_row_ptr[node]);
    int end = __ldg(&g_row_ptr[node + 1]);
    float di = __ldg(&g_dinv[node]);
    float sw = di * di;   // self-loop weight

    float4 acc = ((const float4*)b)[lane];
    float4 t = ((const float4*)(g_T + (size_t)node * HID))[lane];
    acc.x += t.x * sw; acc.y += t.y * sw; acc.z += t.z * sw; acc.w += t.w * sw;

    int e = beg;
    for (; e + 4 <= end; e += 4) {
        int   s0 = __ldg(&g_col_src[e + 0]);
        int   s1 = __ldg(&g_col_src[e + 1]);
        int   s2 = __ldg(&g_col_src[e + 2]);
        int   s3 = __ldg(&g_col_src[e + 3]);
        float w0 = __ldg(&g_col_w[e + 0]);
        float w1 = __ldg(&g_col_w[e + 1]);
        float w2 = __ldg(&g_col_w[e + 2]);
        float w3 = __ldg(&g_col_w[e + 3]);
        float4 v0 = ((const float4*)(g_T + (size_t)s0 * HID))[lane];
        float4 v1 = ((const float4*)(g_T + (size_t)s1 * HID))[lane];
        float4 v2 = ((const float4*)(g_T + (size_t)s2 * HID))[lane];
        float4 v3 = ((const float4*)(g_T + (size_t)s3 * HID))[lane];
        acc.x += v0.x * w0; acc.y += v0.y * w0; acc.z += v0.z * w0; acc.w += v0.w * w0;
        acc.x += v1.x * w1; acc.y += v1.y * w1; acc.z += v1.z * w1; acc.w += v1.w * w1;
        acc.x += v2.x * w2; acc.y += v2.y * w2; acc.z += v2.z * w2; acc.w += v2.w * w2;
        acc.x += v3.x * w3; acc.y += v3.y * w3; acc.z += v3.z * w3; acc.w += v3.w * w3;
    }
    for (; e < end; e++) {
        int   s = __ldg(&g_col_src[e]);
        float w = __ldg(&g_col_w[e]);
        float4 v = ((const float4*)(g_T + (size_t)s * HID))[lane];
        acc.x += v.x * w; acc.y += v.y * w; acc.z += v.z * w; acc.w += v.w * w;
    }
    ((float4*)(g_A + (size_t)node * HID))[lane] = acc;
}

// ---------------- pooling ----------------
__global__ void k_zero_pool() {
    int i = blockIdx.x * blockDim.x + threadIdx.x;
    if (i < N_GRAPHS * HID) g_pool[i] = 0.f;
    if (i < N_GRAPHS) g_cnt[i] = 0.f;
}

__global__ void k_pool(const int* __restrict__ batch) {
    int w = (blockIdx.x * blockDim.x + threadIdx.x) >> 5;
    int lane = threadIdx.x & 31;
    if (w >= N_NODES) return;
    int g = __ldg(&batch[w]);
    float4 v = ((const float4*)(g_A + (size_t)w * HID))[lane];
    v.x = fmaxf(v.x, 0.f); v.y = fmaxf(v.y, 0.f);
    v.z = fmaxf(v.z, 0.f); v.w = fmaxf(v.w, 0.f);
    float* d = g_pool + g * HID + lane * 4;
    asm volatile("red.global.add.v4.f32 [%0], {%1,%2,%3,%4};"
                 :: "l"(d), "f"(v.x), "f"(v.y), "f"(v.z), "f"(v.w) : "memory");
    if (lane == 0) atomicAdd(&g_cnt[g], 1.0f);
}

// ---------------- head: out[g] = sigmoid(mean_pool . Wc + bc) ----------------
__global__ void k_final(const float* __restrict__ Wc, const float* __restrict__ bc,
                        float* __restrict__ out) {
    int g = blockIdx.x;
    int c = threadIdx.x;     // 128
    float cn = fmaxf(g_cnt[g], 1.0f);
    float v = g_pool[g * HID + c] / cn * Wc[c];
    #pragma unroll
    for (int o = 16; o > 0; o >>= 1) v += __shfl_down_sync(0xffffffffu, v, o);
    __shared__ float ss[4];
    if ((c & 31) == 0) ss[c >> 5] = v;
    __syncthreads();
    if (c == 0) {
        float s = ss[0] + ss[1] + ss[2] + ss[3] + bc[0];
        out[g] = 1.0f / (1.0f + expf(-s));
    }
}

// ---------------- launch ----------------
extern "C" void kernel_launch(void* const* d_in, const int* in_sizes, int n_in,
                              void* d_out, int out_size) {
    const float* x   = (const float*)d_in[0];
    const int*   ei  = (const int*)d_in[1];
    const float* ew  = (const float*)d_in[2];
    const int*   bat = (const int*)d_in[3];
    const float* W[4]  = { (const float*)d_in[4], (const float*)d_in[6],
                           (const float*)d_in[8], (const float*)d_in[10] };
    const float* B[4]  = { (const float*)d_in[5], (const float*)d_in[7],
                           (const float*)d_in[9], (const float*)d_in[11] };
    const float* Wc  = (const float*)d_in[12];
    const float* bc  = (const float*)d_in[13];
    float* out = (float*)d_out;

    const int smem = (HID * HID + TILE_R * HID) * sizeof(float);
    cudaFuncSetAttribute(k_gemm, cudaFuncAttributeMaxDynamicSharedMemorySize, smem);

    float* T_ptr; cudaGetSymbolAddress((void**)&T_ptr, g_T);
    float* A_ptr; cudaGetSymbolAddress((void**)&A_ptr, g_A);

    // ---- preprocessing (once per call): degrees + CSR build ----
    k_init_deg<<<(N_NODES + 255) / 256, 256>>>();
    k_accum_deg<<<(N_EDGES + 255) / 256, 256>>>(ei, ew);
    k_dinv<<<(N_NODES + 255) / 256, 256>>>();
    k_scan<<<1, SCAN_T>>>();
    k_fill<<<(N_EDGES + 255) / 256, 256>>>(ei, ew);

    const int gemm_grid = N_NODES / TILE_R;                  // 3125 (exact)
    const int aggr_grid = (N_NODES * 32 + 255) / 256;        // warp per node

    // ---- 4 GCN layers ----
    for (int l = 0; l < 4; l++) {
        const float* in = (l == 0) ? x : A_ptr;
        int relu_in = (l == 0) ? 0 : 1;
        k_gemm<<<gemm_grid, 256, smem>>>(in, W[l], T_ptr, relu_in);
        k_aggregate<<<aggr_grid, 256>>>(B[l]);
    }

    // ---- pooling + head ----
    k_zero_pool<<<(N_GRAPHS * HID + 255) / 256, 256>>>();
    k_pool<<<(N_NODES * 32 + 255) / 256, 256>>>(bat);
    k_final<<<N_GRAPHS, HID>>>(Wc, bc, out);
}

// round 4
// speedup vs baseline: 2.2895x; 1.1381x over previous
#include <cuda_runtime.h>
#include <cuda_bf16.h>

#define N_NODES 100000
#define N_EDGES 3200000
#define HID 128
#define N_GRAPHS 512

// ---------------- scratch (device globals; no allocation allowed) ----------
__device__ float g_T[(size_t)N_NODES * HID];     // tmp = act(input) @ W
__device__ float g_A[(size_t)N_NODES * HID];     // aggregated output
__device__ float g_deg[N_NODES];
__device__ float g_dinv[N_NODES];
__device__ float g_pool[N_GRAPHS * HID];
__device__ float g_cnt[N_GRAPHS];
// CSR (by destination)
__device__ int   g_row_ptr[N_NODES + 1];
__device__ int   g_row_fill[N_NODES];
__device__ int   g_col_src[N_EDGES];
__device__ float g_col_w[N_EDGES];
__device__ int   g_hist[N_NODES];

#define SCAN_BLK 391            // ceil(100000/256)
__device__ int   g_bsum[512];   // block sums (padded)

// ---------------- degree / norm ----------------
__global__ void k_init_deg() {
    int i = blockIdx.x * blockDim.x + threadIdx.x;
    if (i < N_NODES) { g_deg[i] = 1.0f; g_hist[i] = 0; }   // self-loop weight
}

__global__ void k_accum_deg(const int* __restrict__ ei, const float* __restrict__ ew) {
    int e = blockIdx.x * blockDim.x + threadIdx.x;
    if (e >= N_EDGES) return;
    int dst = ei[N_EDGES + e];
    atomicAdd(&g_deg[dst], ew[e]);
    atomicAdd(&g_hist[dst], 1);
}

__global__ void k_dinv() {
    int i = blockIdx.x * blockDim.x + threadIdx.x;
    if (i < N_NODES) g_dinv[i] = rsqrtf(g_deg[i]);   // deg >= 1 always
}

// ---------------- 3-phase parallel exclusive scan over g_hist --------------
// phase 1: per-block sums
__global__ void k_scan1() {
    __shared__ int sh[256];
    int i = blockIdx.x * 256 + threadIdx.x;
    int v = (i < N_NODES) ? g_hist[i] : 0;
    sh[threadIdx.x] = v;
    __syncthreads();
    #pragma unroll
    for (int o = 128; o > 0; o >>= 1) {
        if (threadIdx.x < o) sh[threadIdx.x] += sh[threadIdx.x + o];
        __syncthreads();
    }
    if (threadIdx.x == 0) g_bsum[blockIdx.x] = sh[0];
}

// phase 2: exclusive scan of 391 block sums (single block, 512 threads)
__global__ void k_scan2() {
    __shared__ int sh[512];
    int t = threadIdx.x;
    sh[t] = (t < SCAN_BLK) ? g_bsum[t] : 0;
    __syncthreads();
    #pragma unroll
    for (int o = 1; o < 512; o <<= 1) {
        int v = (t >= o) ? sh[t - o] : 0;
        __syncthreads();
        sh[t] += v;
        __syncthreads();
    }
    if (t < SCAN_BLK) g_bsum[t] = (t == 0) ? 0 : sh[t - 1];   // exclusive
}

// phase 3: per-block local exclusive scan + global offset
__global__ void k_scan3() {
    __shared__ int sh[256];
    int t = threadIdx.x;
    int i = blockIdx.x * 256 + t;
    int v = (i < N_NODES) ? g_hist[i] : 0;
    sh[t] = v;
    __syncthreads();
    #pragma unroll
    for (int o = 1; o < 256; o <<= 1) {
        int u = (t >= o) ? sh[t - o] : 0;
        __syncthreads();
        sh[t] += u;
        __syncthreads();
    }
    if (i < N_NODES) {
        int off = g_bsum[blockIdx.x] + sh[t] - v;   // exclusive
        g_row_ptr[i] = off;
        g_row_fill[i] = off;
    }
    if (i == 0) g_row_ptr[N_NODES] = N_EDGES;       // total statically known
}

// ---------------- fill CSR: col_src + fused norm weight --------------------
__global__ void k_fill(const int* __restrict__ ei, const float* __restrict__ ew) {
    int e = blockIdx.x * blockDim.x + threadIdx.x;
    if (e >= N_EDGES) return;
    int src = ei[e], dst = ei[N_EDGES + e];
    int pos = atomicAdd(&g_row_fill[dst], 1);
    g_col_src[pos] = src;
    g_col_w[pos] = g_dinv[src] * ew[e] * g_dinv[dst];
}

// ---------------- GEMM: T = act(X) @ W ----------------
// 128x128 tile, 256 threads, 8x8 register tile. Xs stored k-major (transposed)
// so both operands load as LDS.128 and x broadcasts across lanes.
#define GTILE 128
__global__ void __launch_bounds__(256) k_gemm(const float* __restrict__ X,
                                              const float* __restrict__ W,
                                              float* __restrict__ T, int relu_in) {
    extern __shared__ float sh[];
    float* Ws = sh;               // Ws[k][c]  128*128
    float* Xs = sh + HID * HID;   // Xs[k][r]  128*128 (transposed)
    int tid = threadIdx.x;
    int row0 = blockIdx.x * GTILE;

    const float4* W4 = (const float4*)W;
    float4* Ws4 = (float4*)Ws;
    #pragma unroll 4
    for (int i = tid; i < HID * HID / 4; i += 256) Ws4[i] = W4[i];

    // load X tile transposed: i -> row = i&127, kgroup = i>>7 (0..31)
    #pragma unroll 4
    for (int i = tid; i < GTILE * (HID / 4); i += 256) {
        int row = i & (GTILE - 1);
        int kg = i >> 7;
        int grow = row0 + row;
        float4 v = make_float4(0.f, 0.f, 0.f, 0.f);
        if (grow < N_NODES) {
            v = *(const float4*)(X + (size_t)grow * HID + kg * 4);
            if (relu_in) {
                v.x = fmaxf(v.x, 0.f); v.y = fmaxf(v.y, 0.f);
                v.z = fmaxf(v.z, 0.f); v.w = fmaxf(v.w, 0.f);
            }
        }
        Xs[(kg * 4 + 0) * GTILE + row] = v.x;
        Xs[(kg * 4 + 1) * GTILE + row] = v.y;
        Xs[(kg * 4 + 2) * GTILE + row] = v.z;
        Xs[(kg * 4 + 3) * GTILE + row] = v.w;
    }
    __syncthreads();

    int tx = tid & 15;   // col group: cols tx*8 .. tx*8+7
    int ty = tid >> 4;   // row group: rows ty*8 .. ty*8+7
    float acc[8][8];
    #pragma unroll
    for (int i = 0; i < 8; i++)
        #pragma unroll
        for (int j = 0; j < 8; j++) acc[i][j] = 0.f;

    const float* xbase = Xs + ty * 8;
    const float* wbase = Ws + tx * 8;
    #pragma unroll 2
    for (int k = 0; k < HID; k++) {
        float4 xlo = *(const float4*)(xbase + k * GTILE);
        float4 xhi = *(const float4*)(xbase + k * GTILE + 4);
        float4 wlo = *(const float4*)(wbase + k * HID);
        float4 whi = *(const float4*)(wbase + k * HID + 4);
        float xv[8] = { xlo.x, xlo.y, xlo.z, xlo.w, xhi.x, xhi.y, xhi.z, xhi.w };
        float wv[8] = { wlo.x, wlo.y, wlo.z, wlo.w, whi.x, whi.y, whi.z, whi.w };
        #pragma unroll
        for (int i = 0; i < 8; i++)
            #pragma unroll
            for (int j = 0; j < 8; j++)
                acc[i][j] += xv[i] * wv[j];
    }

    #pragma unroll
    for (int i = 0; i < 8; i++) {
        int grow = row0 + ty * 8 + i;
        if (grow < N_NODES) {
            float* dst = T + (size_t)grow * HID + tx * 8;
            *(float4*)dst       = make_float4(acc[i][0], acc[i][1], acc[i][2], acc[i][3]);
            *(float4*)(dst + 4) = make_float4(acc[i][4], acc[i][5], acc[i][6], acc[i][7]);
        }
    }
}

// ---------------- aggregate: A[d] = b + T[d]*dinv[d]^2 + sum_e w_e*T[src_e] ----
// warp per destination node; lane owns one float4 (4 columns)
__global__ void k_aggregate(const float* __restrict__ b) {
    int node = (blockIdx.x * blockDim.x + threadIdx.x) >> 5;
    int lane = threadIdx.x & 31;
    if (node >= N_NODES) return;

    int beg = __ldg(&g_row_ptr[node]);
    int end = __ldg(&g_row_ptr[node + 1]);
    float di = __ldg(&g_dinv[node]);
    float sw = di * di;   // self-loop weight

    float4 acc = ((const float4*)b)[lane];
    float4 t = ((const float4*)(g_T + (size_t)node * HID))[lane];
    acc.x += t.x * sw; acc.y += t.y * sw; acc.z += t.z * sw; acc.w += t.w * sw;

    int e = beg;
    for (; e + 4 <= end; e += 4) {
        int   s0 = __ldg(&g_col_src[e + 0]);
        int   s1 = __ldg(&g_col_src[e + 1]);
        int   s2 = __ldg(&g_col_src[e + 2]);
        int   s3 = __ldg(&g_col_src[e + 3]);
        float w0 = __ldg(&g_col_w[e + 0]);
        float w1 = __ldg(&g_col_w[e + 1]);
        float w2 = __ldg(&g_col_w[e + 2]);
        float w3 = __ldg(&g_col_w[e + 3]);
        float4 v0 = ((const float4*)(g_T + (size_t)s0 * HID))[lane];
        float4 v1 = ((const float4*)(g_T + (size_t)s1 * HID))[lane];
        float4 v2 = ((const float4*)(g_T + (size_t)s2 * HID))[lane];
        float4 v3 = ((const float4*)(g_T + (size_t)s3 * HID))[lane];
        acc.x += v0.x * w0; acc.y += v0.y * w0; acc.z += v0.z * w0; acc.w += v0.w * w0;
        acc.x += v1.x * w1; acc.y += v1.y * w1; acc.z += v1.z * w1; acc.w += v1.w * w1;
        acc.x += v2.x * w2; acc.y += v2.y * w2; acc.z += v2.z * w2; acc.w += v2.w * w2;
        acc.x += v3.x * w3; acc.y += v3.y * w3; acc.z += v3.z * w3; acc.w += v3.w * w3;
    }
    for (; e < end; e++) {
        int   s = __ldg(&g_col_src[e]);
        float w = __ldg(&g_col_w[e]);
        float4 v = ((const float4*)(g_T + (size_t)s * HID))[lane];
        acc.x += v.x * w; acc.y += v.y * w; acc.z += v.z * w; acc.w += v.w * w;
    }
    ((float4*)(g_A + (size_t)node * HID))[lane] = acc;
}

// ---------------- pooling ----------------
__global__ void k_zero_pool() {
    int i = blockIdx.x * blockDim.x + threadIdx.x;
    if (i < N_GRAPHS * HID) g_pool[i] = 0.f;
    if (i < N_GRAPHS) g_cnt[i] = 0.f;
}

__global__ void k_pool(const int* __restrict__ batch) {
    int w = (blockIdx.x * blockDim.x + threadIdx.x) >> 5;
    int lane = threadIdx.x & 31;
    if (w >= N_NODES) return;
    int g = __ldg(&batch[w]);
    float4 v = ((const float4*)(g_A + (size_t)w * HID))[lane];
    v.x = fmaxf(v.x, 0.f); v.y = fmaxf(v.y, 0.f);
    v.z = fmaxf(v.z, 0.f); v.w = fmaxf(v.w, 0.f);
    float* d = g_pool + g * HID + lane * 4;
    asm volatile("red.global.add.v4.f32 [%0], {%1,%2,%3,%4};"
                 :: "l"(d), "f"(v.x), "f"(v.y), "f"(v.z), "f"(v.w) : "memory");
    if (lane == 0) atomicAdd(&g_cnt[g], 1.0f);
}

// ---------------- head: out[g] = sigmoid(mean_pool . Wc + bc) ----------------
__global__ void k_final(const float* __restrict__ Wc, const float* __restrict__ bc,
                        float* __restrict__ out) {
    int g = blockIdx.x;
    int c = threadIdx.x;     // 128
    float cn = fmaxf(g_cnt[g], 1.0f);
    float v = g_pool[g * HID + c] / cn * Wc[c];
    #pragma unroll
    for (int o = 16; o > 0; o >>= 1) v += __shfl_down_sync(0xffffffffu, v, o);
    __shared__ float ss[4];
    if ((c & 31) == 0) ss[c >> 5] = v;
    __syncthreads();
    if (c == 0) {
        float s = ss[0] + ss[1] + ss[2] + ss[3] + bc[0];
        out[g] = 1.0f / (1.0f + expf(-s));
    }
}

// ---------------- launch ----------------
extern "C" void kernel_launch(void* const* d_in, const int* in_sizes, int n_in,
                              void* d_out, int out_size) {
    const float* x   = (const float*)d_in[0];
    const int*   ei  = (const int*)d_in[1];
    const float* ew  = (const float*)d_in[2];
    const int*   bat = (const int*)d_in[3];
    const float* W[4]  = { (const float*)d_in[4], (const float*)d_in[6],
                           (const float*)d_in[8], (const float*)d_in[10] };
    const float* B[4]  = { (const float*)d_in[5], (const float*)d_in[7],
                           (const float*)d_in[9], (const float*)d_in[11] };
    const float* Wc  = (const float*)d_in[12];
    const float* bc  = (const float*)d_in[13];
    float* out = (float*)d_out;

    const int smem = 2 * HID * HID * sizeof(float);   // 128KB
    cudaFuncSetAttribute(k_gemm, cudaFuncAttributeMaxDynamicSharedMemorySize, smem);

    float* T_ptr; cudaGetSymbolAddress((void**)&T_ptr, g_T);
    float* A_ptr; cudaGetSymbolAddress((void**)&A_ptr, g_A);

    // ---- preprocessing: degrees + CSR build ----
    k_init_deg<<<(N_NODES + 255) / 256, 256>>>();
    k_accum_deg<<<(N_EDGES + 255) / 256, 256>>>(ei, ew);
    k_dinv<<<(N_NODES + 255) / 256, 256>>>();
    k_scan1<<<SCAN_BLK, 256>>>();
    k_scan2<<<1, 512>>>();
    k_scan3<<<SCAN_BLK, 256>>>();
    k_fill<<<(N_EDGES + 255) / 256, 256>>>(ei, ew);

    const int gemm_grid = (N_NODES + GTILE - 1) / GTILE;     // 782
    const int aggr_grid = (N_NODES * 32 + 255) / 256;        // warp per node

    // ---- 4 GCN layers ----
    for (int l = 0; l < 4; l++) {
        const float* in = (l == 0) ? x : A_ptr;
        int relu_in = (l == 0) ? 0 : 1;
        k_gemm<<<gemm_grid, 256, smem>>>(in, W[l], T_ptr, relu_in);
        k_aggregate<<<aggr_grid, 256>>>(B[l]);
    }

    // ---- pooling + head ----
    k_zero_pool<<<(N_GRAPHS * HID + 255) / 256, 256>>>();
    k_pool<<<(N_NODES * 32 + 255) / 256, 256>>>(bat);
    k_final<<<N_GRAPHS, HID>>>(Wc, bc, out);
}

// round 6
// speedup vs baseline: 3.2195x; 1.4062x over previous
#include <cuda_runtime.h>
#include <cuda_bf16.h>
#include <cstdint>

#define N_NODES 100000
#define N_EDGES 3200000
#define HID 128
#define N_GRAPHS 512

// ---------------- scratch (device globals; no allocation allowed) ----------
__device__ float g_T[(size_t)N_NODES * HID];     // tmp = act(input) @ W
__device__ float g_A[(size_t)N_NODES * HID];     // aggregated output
__device__ float g_deg[N_NODES];
__device__ float g_dinv[N_NODES];
__device__ float g_pool[N_GRAPHS * HID];
__device__ float g_cnt[N_GRAPHS];
// CSR (by destination)
__device__ int   g_row_ptr[N_NODES + 1];
__device__ int   g_row_fill[N_NODES];
__device__ int   g_col_src[N_EDGES];
__device__ float g_col_w[N_EDGES];
__device__ int   g_hist[N_NODES];

#define SCAN_BLK 391            // ceil(100000/256)
__device__ int   g_bsum[512];   // block sums (padded)

// tf32 B-fragments for all 4 layers:
// layout [layer][s2(8)][t(16)][lane(32)] -> float4 = (b0_even, b1_even, b0_odd, b1_odd)
__device__ float4 g_Wfrag[4 * 8 * 16 * 32];

__device__ __forceinline__ uint32_t cvt_tf32(float f) {
    uint32_t u;
    asm("cvt.rna.tf32.f32 %0, %1;" : "=r"(u) : "f"(f));
    return u;
}

// ---------------- degree / norm ----------------
__global__ void k_init_deg() {
    int i = blockIdx.x * blockDim.x + threadIdx.x;
    if (i < N_NODES) { g_deg[i] = 1.0f; g_hist[i] = 0; }   // self-loop weight
}

__global__ void k_accum_deg(const int* __restrict__ ei, const float* __restrict__ ew) {
    int e = blockIdx.x * blockDim.x + threadIdx.x;
    if (e >= N_EDGES) return;
    int dst = ei[N_EDGES + e];
    atomicAdd(&g_deg[dst], ew[e]);
    atomicAdd(&g_hist[dst], 1);
}

__global__ void k_dinv() {
    int i = blockIdx.x * blockDim.x + threadIdx.x;
    if (i < N_NODES) g_dinv[i] = rsqrtf(g_deg[i]);   // deg >= 1 always
}

// ---------------- 3-phase parallel exclusive scan over g_hist --------------
__global__ void k_scan1() {
    __shared__ int sh[256];
    int i = blockIdx.x * 256 + threadIdx.x;
    int v = (i < N_NODES) ? g_hist[i] : 0;
    sh[threadIdx.x] = v;
    __syncthreads();
    #pragma unroll
    for (int o = 128; o > 0; o >>= 1) {
        if (threadIdx.x < o) sh[threadIdx.x] += sh[threadIdx.x + o];
        __syncthreads();
    }
    if (threadIdx.x == 0) g_bsum[blockIdx.x] = sh[0];
}

__global__ void k_scan2() {
    __shared__ int sh[512];
    int t = threadIdx.x;
    sh[t] = (t < SCAN_BLK) ? g_bsum[t] : 0;
    __syncthreads();
    #pragma unroll
    for (int o = 1; o < 512; o <<= 1) {
        int v = (t >= o) ? sh[t - o] : 0;
        __syncthreads();
        sh[t] += v;
        __syncthreads();
    }
    if (t < SCAN_BLK) g_bsum[t] = (t == 0) ? 0 : sh[t - 1];   // exclusive
}

__global__ void k_scan3() {
    __shared__ int sh[256];
    int t = threadIdx.x;
    int i = blockIdx.x * 256 + t;
    int v = (i < N_NODES) ? g_hist[i] : 0;
    sh[t] = v;
    __syncthreads();
    #pragma unroll
    for (int o = 1; o < 256; o <<= 1) {
        int u = (t >= o) ? sh[t - o] : 0;
        __syncthreads();
        sh[t] += u;
        __syncthreads();
    }
    if (i < N_NODES) {
        int off = g_bsum[blockIdx.x] + sh[t] - v;   // exclusive
        g_row_ptr[i] = off;
        g_row_fill[i] = off;
    }
    if (i == 0) g_row_ptr[N_NODES] = N_EDGES;
}

// ---------------- fill CSR: col_src + fused norm weight --------------------
__global__ void k_fill(const int* __restrict__ ei, const float* __restrict__ ew) {
    int e = blockIdx.x * blockDim.x + threadIdx.x;
    if (e >= N_EDGES) return;
    int src = ei[e], dst = ei[N_EDGES + e];
    int pos = atomicAdd(&g_row_fill[dst], 1);
    g_col_src[pos] = src;
    g_col_w[pos] = g_dinv[src] * ew[e] * g_dinv[dst];
}

// ---------------- precompute W tf32 fragments (all 4 layers) ---------------
// b0 for mma (col-major B, n8k8): (k=tg, n=gid); b1: (k=tg+4, n=gid)
__global__ void k_wfrag(const float* __restrict__ W0, const float* __restrict__ W1,
                        const float* __restrict__ W2, const float* __restrict__ W3) {
    int idx = blockIdx.x * 256 + threadIdx.x;     // 4*8*16*32 = 16384
    if (idx >= 4 * 8 * 16 * 32) return;
    int layer = idx >> 12;
    int rem = idx & 4095;
    int s2 = rem >> 9;           // k-step pair (0..7)
    int t  = (rem >> 5) & 15;    // n-tile (0..15)
    int lane = rem & 31;
    int tg = lane & 3, gid = lane >> 2;
    const float* W = (layer == 0) ? W0 : (layer == 1) ? W1 : (layer == 2) ? W2 : W3;
    int n = t * 8 + gid;
    int k0 = s2 * 16;
    float4 v;
    v.x = __uint_as_float(cvt_tf32(W[(k0 + tg) * HID + n]));
    v.y = __uint_as_float(cvt_tf32(W[(k0 + tg + 4) * HID + n]));
    v.z = __uint_as_float(cvt_tf32(W[(k0 + 8 + tg) * HID + n]));
    v.w = __uint_as_float(cvt_tf32(W[(k0 + 12 + tg) * HID + n]));
    g_Wfrag[idx] = v;
}

// ---------------- GEMM via mma.sync tf32: T = act(X) @ W ------------------
// 128x128 tile per block, 8 warps, warp w owns rows w*16..w*16+15, all 128 cols.
#define GTILE 128
#define XS_STRIDE 132
#define GEMM_SMEM (GTILE * XS_STRIDE * 4)

__device__ __forceinline__ void mma_tf32(float* d, uint32_t a0, uint32_t a1,
                                         uint32_t a2, uint32_t a3,
                                         float bx, float by) {
    asm volatile(
        "mma.sync.aligned.m16n8k8.row.col.f32.tf32.tf32.f32 "
        "{%0,%1,%2,%3}, {%4,%5,%6,%7}, {%8,%9}, {%0,%1,%2,%3};"
        : "+f"(d[0]), "+f"(d[1]), "+f"(d[2]), "+f"(d[3])
        : "r"(a0), "r"(a1), "r"(a2), "r"(a3),
          "r"(__float_as_uint(bx)), "r"(__float_as_uint(by)));
}

__global__ void __launch_bounds__(256) k_gemm_mma(const float* __restrict__ X,
                                                  float* __restrict__ T,
                                                  int layer, int relu_in) {
    extern __shared__ uint32_t Xs[];   // [128][132] tf32 bits
    int tid = threadIdx.x;
    int wid = tid >> 5;
    int lane = tid & 31;
    int row0 = blockIdx.x * GTILE;

    // stage X tile (relu + tf32 convert)
    #pragma unroll
    for (int it = 0; it < 16; it++) {
        int i = tid + it * 256;            // row = i>>5, kg = i&31
        int row = i >> 5;
        int kg = i & 31;
        int grow = row0 + row;
        float4 v = make_float4(0.f, 0.f, 0.f, 0.f);
        if (grow < N_NODES) {
            v = *(const float4*)(X + (size_t)grow * HID + kg * 4);
            if (relu_in) {
                v.x = fmaxf(v.x, 0.f); v.y = fmaxf(v.y, 0.f);
                v.z = fmaxf(v.z, 0.f); v.w = fmaxf(v.w, 0.f);
            }
        }
        uint32_t* dst = Xs + row * XS_STRIDE + kg * 4;
        dst[0] = cvt_tf32(v.x); dst[1] = cvt_tf32(v.y);
        dst[2] = cvt_tf32(v.z); dst[3] = cvt_tf32(v.w);
    }
    __syncthreads();

    int tg = lane & 3, gid = lane >> 2;
    float acc[16][4];
    #pragma unroll
    for (int t = 0; t < 16; t++)
        #pragma unroll
        for (int j = 0; j < 4; j++) acc[t][j] = 0.f;

    const uint32_t* arow_lo = Xs + (wid * 16 + gid) * XS_STRIDE;
    const uint32_t* arow_hi = arow_lo + 8 * XS_STRIDE;
    const float4* frag = g_Wfrag + (size_t)layer * 4096 + lane;

    #pragma unroll
    for (int s2 = 0; s2 < 8; s2++) {
        int k0 = s2 * 16;
        // A fragments for k-steps 2*s2 (even: cols k0+tg, k0+tg+4) and 2*s2+1
        uint32_t ae0 = arow_lo[k0 + tg];
        uint32_t ae1 = arow_hi[k0 + tg];
        uint32_t ae2 = arow_lo[k0 + tg + 4];
        uint32_t ae3 = arow_hi[k0 + tg + 4];
        uint32_t ao0 = arow_lo[k0 + 8 + tg];
        uint32_t ao1 = arow_hi[k0 + 8 + tg];
        uint32_t ao2 = arow_lo[k0 + 12 + tg];
        uint32_t ao3 = arow_hi[k0 + 12 + tg];
        const float4* f = frag + s2 * 512;   // [t][lane] stride 32
        #pragma unroll
        for (int t = 0; t < 16; t++) {
            float4 b = f[t * 32];
            mma_tf32(acc[t], ae0, ae1, ae2, ae3, b.x, b.y);
            mma_tf32(acc[t], ao0, ao1, ao2, ao3, b.z, b.w);
        }
    }

    // epilogue: D layout m16n8 -> d0,d1: (gid, tg*2 / tg*2+1); d2,d3: (gid+8, ...)
    int row_lo = row0 + wid * 16 + gid;
    int row_hi = row_lo + 8;
    #pragma unroll
    for (int t = 0; t < 16; t++) {
        int col = t * 8 + tg * 2;
        if (row_lo < N_NODES)
            *(float2*)(T + (size_t)row_lo * HID + col) = make_float2(acc[t][0], acc[t][1]);
        if (row_hi < N_NODES)
            *(float2*)(T + (size_t)row_hi * HID + col) = make_float2(acc[t][2], acc[t][3]);
    }
}

// ---------------- aggregate: A[d] = b + T[d]*dinv[d]^2 + sum_e w_e*T[src_e] ----
__global__ void k_aggregate(const float* __restrict__ b) {
    int node = (blockIdx.x * blockDim.x + threadIdx.x) >> 5;
    int lane = threadIdx.x & 31;
    if (node >= N_NODES) return;

    int beg = __ldg(&g_row_ptr[node]);
    int end = __ldg(&g_row_ptr[node + 1]);
    float di = __ldg(&g_dinv[node]);
    float sw = di * di;   // self-loop weight

    float4 acc = ((const float4*)b)[lane];
    float4 t = ((const float4*)(g_T + (size_t)node * HID))[lane];
    acc.x += t.x * sw; acc.y += t.y * sw; acc.z += t.z * sw; acc.w += t.w * sw;

    int e = beg;
    for (; e + 4 <= end; e += 4) {
        int   s0 = __ldg(&g_col_src[e + 0]);
        int   s1 = __ldg(&g_col_src[e + 1]);
        int   s2 = __ldg(&g_col_src[e + 2]);
        int   s3 = __ldg(&g_col_src[e + 3]);
        float w0 = __ldg(&g_col_w[e + 0]);
        float w1 = __ldg(&g_col_w[e + 1]);
        float w2 = __ldg(&g_col_w[e + 2]);
        float w3 = __ldg(&g_col_w[e + 3]);
        float4 v0 = ((const float4*)(g_T + (size_t)s0 * HID))[lane];
        float4 v1 = ((const float4*)(g_T + (size_t)s1 * HID))[lane];
        float4 v2 = ((const float4*)(g_T + (size_t)s2 * HID))[lane];
        float4 v3 = ((const float4*)(g_T + (size_t)s3 * HID))[lane];
        acc.x += v0.x * w0; acc.y += v0.y * w0; acc.z += v0.z * w0; acc.w += v0.w * w0;
        acc.x += v1.x * w1; acc.y += v1.y * w1; acc.z += v1.z * w1; acc.w += v1.w * w1;
        acc.x += v2.x * w2; acc.y += v2.y * w2; acc.z += v2.z * w2; acc.w += v2.w * w2;
        acc.x += v3.x * w3; acc.y += v3.y * w3; acc.z += v3.z * w3; acc.w += v3.w * w3;
    }
    for (; e < end; e++) {
        int   s = __ldg(&g_col_src[e]);
        float w = __ldg(&g_col_w[e]);
        float4 v = ((const float4*)(g_T + (size_t)s * HID))[lane];
        acc.x += v.x * w; acc.y += v.y * w; acc.z += v.z * w; acc.w += v.w * w;
    }
    ((float4*)(g_A + (size_t)node * HID))[lane] = acc;
}

// ---------------- pooling ----------------
__global__ void k_zero_pool() {
    int i = blockIdx.x * blockDim.x + threadIdx.x;
    if (i < N_GRAPHS * HID) g_pool[i] = 0.f;
    if (i < N_GRAPHS) g_cnt[i] = 0.f;
}

__global__ void k_pool(const int* __restrict__ batch) {
    int w = (blockIdx.x * blockDim.x + threadIdx.x) >> 5;
    int lane = threadIdx.x & 31;
    if (w >= N_NODES) return;
    int g = __ldg(&batch[w]);
    float4 v = ((const float4*)(g_A + (size_t)w * HID))[lane];
    v.x = fmaxf(v.x, 0.f); v.y = fmaxf(v.y, 0.f);
    v.z = fmaxf(v.z, 0.f); v.w = fmaxf(v.w, 0.f);
    float* d = g_pool + g * HID + lane * 4;
    asm volatile("red.global.add.v4.f32 [%0], {%1,%2,%3,%4};"
                 :: "l"(d), "f"(v.x), "f"(v.y), "f"(v.z), "f"(v.w) : "memory");
    if (lane == 0) atomicAdd(&g_cnt[g], 1.0f);
}

// ---------------- head ----------------
__global__ void k_final(const float* __restrict__ Wc, const float* __restrict__ bc,
                        float* __restrict__ out) {
    int g = blockIdx.x;
    int c = threadIdx.x;     // 128
    float cn = fmaxf(g_cnt[g], 1.0f);
    float v = g_pool[g * HID + c] / cn * Wc[c];
    #pragma unroll
    for (int o = 16; o > 0; o >>= 1) v += __shfl_down_sync(0xffffffffu, v, o);
    __shared__ float ss[4];
    if ((c & 31) == 0) ss[c >> 5] = v;
    __syncthreads();
    if (c == 0) {
        float s = ss[0] + ss[1] + ss[2] + ss[3] + bc[0];
        out[g] = 1.0f / (1.0f + expf(-s));
    }
}

// ---------------- launch ----------------
extern "C" void kernel_launch(void* const* d_in, const int* in_sizes, int n_in,
                              void* d_out, int out_size) {
    const float* x   = (const float*)d_in[0];
    const int*   ei  = (const int*)d_in[1];
    const float* ew  = (const float*)d_in[2];
    const int*   bat = (const int*)d_in[3];
    const float* W[4]  = { (const float*)d_in[4], (const float*)d_in[6],
                           (const float*)d_in[8], (const float*)d_in[10] };
    const float* B[4]  = { (const float*)d_in[5], (const float*)d_in[7],
                           (const float*)d_in[9], (const float*)d_in[11] };
    const float* Wc  = (const float*)d_in[12];
    const float* bc  = (const float*)d_in[13];
    float* out = (float*)d_out;

    cudaFuncSetAttribute(k_gemm_mma, cudaFuncAttributeMaxDynamicSharedMemorySize,
                         GEMM_SMEM);

    float* T_ptr; cudaGetSymbolAddress((void**)&T_ptr, g_T);
    float* A_ptr; cudaGetSymbolAddress((void**)&A_ptr, g_A);

    // ---- preprocessing: degrees + CSR build + W fragments ----
    k_init_deg<<<(N_NODES + 255) / 256, 256>>>();
    k_accum_deg<<<(N_EDGES + 255) / 256, 256>>>(ei, ew);
    k_dinv<<<(N_NODES + 255) / 256, 256>>>();
    k_scan1<<<SCAN_BLK, 256>>>();
    k_scan2<<<1, 512>>>();
    k_scan3<<<SCAN_BLK, 256>>>();
    k_fill<<<(N_EDGES + 255) / 256, 256>>>(ei, ew);
    k_wfrag<<<64, 256>>>(W[0], W[1], W[2], W[3]);

    const int gemm_grid = (N_NODES + GTILE - 1) / GTILE;     // 782
    const int aggr_grid = (N_NODES * 32 + 255) / 256;        // warp per node

    // ---- 4 GCN layers ----
    for (int l = 0; l < 4; l++) {
        const float* in = (l == 0) ? x : A_ptr;
        int relu_in = (l == 0) ? 0 : 1;
        k_gemm_mma<<<gemm_grid, 256, GEMM_SMEM>>>(in, T_ptr, l, relu_in);
        k_aggregate<<<aggr_grid, 256>>>(B[l]);
    }

    // ---- pooling + head ----
    k_zero_pool<<<(N_GRAPHS * HID + 255) / 256, 256>>>();
    k_pool<<<(N_NODES * 32 + 255) / 256, 256>>>(bat);
    k_final<<<N_GRAPHS, HID>>>(Wc, bc, out);
}